// round 6
// baseline (speedup 1.0000x reference)
#include <cuda_runtime.h>
#include <cuda_bf16.h>
#include <math.h>
#include <stdint.h>

#define N_NODES 100000
#define N_EDGES 1600000
#define DIN 64
#define DHID 128
#define DOUT 40
#define Y2L_STR 48  // padded row stride (192B = 6 sectors, rows sector-aligned)
#define SCAN_B 512
#define SCAN_NB ((N_NODES + SCAN_B - 1) / SCAN_B)
#define TILE_M 128
#define N_TILES ((N_NODES + TILE_M - 1) / TILE_M)  // 782
#define W2ROWS 80
#define LDS_ROW 136  // bf16 elems per SMEM row (128 + 8 pad) -> conflict-free frags

// SMEM byte offsets for fused kernel
#define SM_AH 0
#define SM_AL 34816
#define SM_W1H 69632
#define SM_W1L 104448
#define SM_W2H 139264
#define SM_W2L 161024
#define SM_BIAS 182784
#define SM_TOTAL 183424

// ---------------- device scratch ----------------
__device__ int g_is64;
__device__ int g_deg[N_NODES];
__device__ int g_rowptr[N_NODES + 1];
__device__ int g_fill[N_NODES];
__device__ int g_col[N_EDGES];
__device__ int g_part[256];
__device__ uint32_t g_w1h[DHID * 64], g_w1l[DHID * 64];      // [128 out][128 k] bf16x2
__device__ uint32_t g_w2h[W2ROWS * 64], g_w2l[W2ROWS * 64];  // [80 out][128 k]
__device__ float g_y2l[(size_t)N_NODES * Y2L_STR];
__device__ float g_y2r[(size_t)N_NODES * DOUT];

// ---------------- helpers ----------------
__device__ __forceinline__ void mma16816(float* c, const uint32_t* a,
                                         uint32_t b0, uint32_t b1) {
    asm volatile(
        "mma.sync.aligned.m16n8k16.row.col.f32.bf16.bf16.f32 "
        "{%0,%1,%2,%3}, {%4,%5,%6,%7}, {%8,%9}, {%0,%1,%2,%3};"
        : "+f"(c[0]), "+f"(c[1]), "+f"(c[2]), "+f"(c[3])
        : "r"(a[0]), "r"(a[1]), "r"(a[2]), "r"(a[3]), "r"(b0), "r"(b1));
}
__device__ __forceinline__ void split_bf16(float v, __nv_bfloat16& h, __nv_bfloat16& l) {
    h = __float2bfloat16_rn(v);
    l = __float2bfloat16_rn(v - __bfloat162float(h));
}

// ---------------- edge index access (int64 or int32, runtime-detected) ----
__device__ __forceinline__ int esrc(const void* ei, int e) {
    return g_is64 ? (int)((const long long*)ei)[e] : ((const int*)ei)[e];
}
__device__ __forceinline__ int edst(const void* ei, int e) {
    return g_is64 ? (int)((const long long*)ei)[(size_t)N_EDGES + e]
                  : ((const int*)ei)[(size_t)N_EDGES + e];
}

// init degrees + dtype detect + weight split-conversion (one kernel)
__global__ void k_init(const int* ei,
                       const float* __restrict__ W1l, const float* __restrict__ W1r,
                       const float* __restrict__ W2l, const float* __restrict__ W2r) {
    int i = blockIdx.x * blockDim.x + threadIdx.x;
    if (i < N_NODES) g_deg[i] = 0;
    // weight conversion: first 13312 threads
    int tot1 = DHID * 64;
    if (i < tot1) {
        int o = i >> 6, c = 2 * (i & 63);
        float v0 = (c < 64) ? W1l[o * 64 + c] : W1r[o * 64 + c - 64];
        float v1 = (c < 64) ? W1l[o * 64 + c + 1] : W1r[o * 64 + c - 63];
        __nv_bfloat16 h0, h1, l0, l1;
        split_bf16(v0, h0, l0); split_bf16(v1, h1, l1);
        __nv_bfloat162 ph = __nv_bfloat162(h0, h1);
        __nv_bfloat162 pl = __nv_bfloat162(l0, l1);
        g_w1h[i] = *(uint32_t*)&ph;
        g_w1l[i] = *(uint32_t*)&pl;
    } else if (i < tot1 + W2ROWS * 64) {
        int j = i - tot1;
        int o = j >> 6, c = 2 * (j & 63);
        float v0 = (o < DOUT) ? W2l[o * DHID + c] : W2r[(o - DOUT) * DHID + c];
        float v1 = (o < DOUT) ? W2l[o * DHID + c + 1] : W2r[(o - DOUT) * DHID + c + 1];
        __nv_bfloat16 h0, h1, l0, l1;
        split_bf16(v0, h0, l0); split_bf16(v1, h1, l1);
        __nv_bfloat162 ph = __nv_bfloat162(h0, h1);
        __nv_bfloat162 pl = __nv_bfloat162(l0, l1);
        g_w2h[j] = *(uint32_t*)&ph;
        g_w2l[j] = *(uint32_t*)&pl;
    }
    if (blockIdx.x == 0) {
        bool ok = true;
        for (int j = threadIdx.x; j < 4096; j += blockDim.x)
            if (ei[2 * j + 1] != 0) ok = false;
        int all = __syncthreads_and((int)ok);
        if (threadIdx.x == 0) g_is64 = all ? 1 : 0;
    }
}
__global__ void k_hist(const void* ei) {
    int e = blockIdx.x * blockDim.x + threadIdx.x;
    if (e < N_EDGES) atomicAdd(&g_deg[edst(ei, e)], 1);
}
__global__ void k_scan_block() {
    __shared__ int s[SCAN_B];
    int i = blockIdx.x * SCAN_B + threadIdx.x;
    int v = (i < N_NODES) ? g_deg[i] : 0;
    s[threadIdx.x] = v;
    __syncthreads();
    for (int off = 1; off < SCAN_B; off <<= 1) {
        int t = (threadIdx.x >= off) ? s[threadIdx.x - off] : 0;
        __syncthreads();
        s[threadIdx.x] += t;
        __syncthreads();
    }
    if (i < N_NODES) g_rowptr[i] = s[threadIdx.x] - v;
    if (threadIdx.x == SCAN_B - 1) g_part[blockIdx.x] = s[SCAN_B - 1];
}
// each block redundantly scans the 196 partials in SMEM, then applies offset
__global__ void k_scan_add() {
    __shared__ int sp[256];
    int t = threadIdx.x;
    if (t < 256) sp[t] = (t < SCAN_NB) ? g_part[t] : 0;
    __syncthreads();
    for (int off = 1; off < 256; off <<= 1) {
        int v = (t < 256 && t >= off) ? sp[t - off] : 0;
        __syncthreads();
        if (t < 256) sp[t] += v;
        __syncthreads();
    }
    int offset = (blockIdx.x == 0) ? 0 : sp[blockIdx.x - 1];
    int i = blockIdx.x * SCAN_B + t;
    if (i < N_NODES) {
        int r = g_rowptr[i] + offset;
        g_rowptr[i] = r;
        g_fill[i] = r;
    }
    if (i == 0) g_rowptr[N_NODES] = N_EDGES;
}
__global__ void k_scatter(const void* ei) {
    int e = blockIdx.x * blockDim.x + threadIdx.x;
    if (e < N_EDGES) {
        int d = edst(ei, e);
        int p = atomicAdd(&g_fill[d], 1);
        g_col[p] = esrc(ei, e);
    }
}

// ---------------- fused: aggregate + GEMM1 + relu + GEMM2 -----------------
// Per CTA: 128 nodes. A/h1 tiles live entirely in SMEM (no global round-trip).
__global__ void __launch_bounds__(512) k_fused(const float* __restrict__ x,
                                               const float* __restrict__ b1) {
    extern __shared__ char dsm[];
    __nv_bfloat16* sAh = (__nv_bfloat16*)(dsm + SM_AH);
    __nv_bfloat16* sAl = (__nv_bfloat16*)(dsm + SM_AL);
    __nv_bfloat16* sW1h = (__nv_bfloat16*)(dsm + SM_W1H);
    __nv_bfloat16* sW1l = (__nv_bfloat16*)(dsm + SM_W1L);
    __nv_bfloat16* sW2h = (__nv_bfloat16*)(dsm + SM_W2H);
    __nv_bfloat16* sW2l = (__nv_bfloat16*)(dsm + SM_W2L);
    float* sB = (float*)(dsm + SM_BIAS);
    __shared__ int s_row;

    int tid = threadIdx.x, wid = tid >> 5, lane = tid & 31;
    int base = blockIdx.x * TILE_M;

    // ---- stage weights (pre-split bf16 in global) ----
    for (int i = tid; i < 128 * 16; i += 512) {
        int r = i >> 4, c8 = i & 15;
        *(uint4*)((char*)sW1h + r * (LDS_ROW * 2) + c8 * 16) = *(const uint4*)(g_w1h + r * 64 + c8 * 4);
        *(uint4*)((char*)sW1l + r * (LDS_ROW * 2) + c8 * 16) = *(const uint4*)(g_w1l + r * 64 + c8 * 4);
    }
    for (int i = tid; i < W2ROWS * 16; i += 512) {
        int r = i >> 4, c8 = i & 15;
        *(uint4*)((char*)sW2h + r * (LDS_ROW * 2) + c8 * 16) = *(const uint4*)(g_w2h + r * 64 + c8 * 4);
        *(uint4*)((char*)sW2l + r * (LDS_ROW * 2) + c8 * 16) = *(const uint4*)(g_w2l + r * 64 + c8 * 4);
    }
    if (tid < DHID) sB[tid] = b1[tid];
    if (tid == 0) s_row = 0;
    __syncthreads();

    // ---- gather-aggregate + self rows -> split into sAh/sAl ----
    // dynamic row scheduling (degree-variance balance), 4-deep unrolled gather
    for (;;) {
        int r;
        if (lane == 0) r = atomicAdd(&s_row, 1);
        r = __shfl_sync(0xffffffffu, r, 0);
        if (r >= TILE_M) break;
        int n = base + r;
        float a0 = 0.f, a1 = 0.f, b0 = 0.f, b1v = 0.f;
        float c0 = 0.f, c1 = 0.f, d0 = 0.f, d1 = 0.f;
        float s0v = 0.f, s1v = 0.f;
        float inv = 1.f;
        if (n < N_NODES) {
            int s0 = g_rowptr[n], s1 = g_rowptr[n + 1];
            int e = s0;
            for (; e + 3 < s1; e += 4) {
                const float* f0 = x + (size_t)g_col[e] * DIN;
                const float* f1 = x + (size_t)g_col[e + 1] * DIN;
                const float* f2 = x + (size_t)g_col[e + 2] * DIN;
                const float* f3 = x + (size_t)g_col[e + 3] * DIN;
                a0 += f0[lane]; a1 += f0[lane + 32];
                b0 += f1[lane]; b1v += f1[lane + 32];
                c0 += f2[lane]; c1 += f2[lane + 32];
                d0 += f3[lane]; d1 += f3[lane + 32];
            }
            for (; e < s1; e++) {
                const float* f0 = x + (size_t)g_col[e] * DIN;
                a0 += f0[lane]; a1 += f0[lane + 32];
            }
            a0 += b0 + c0 + d0;
            a1 += b1v + c1 + d1;
            inv = 1.f / (float)max(s1 - s0, 1);
            s0v = x[(size_t)n * DIN + lane];
            s1v = x[(size_t)n * DIN + 32 + lane];
        }
        a0 *= inv; a1 *= inv;
        __nv_bfloat16 h, l;
        split_bf16(a0, h, l);
        sAh[r * LDS_ROW + lane] = h; sAl[r * LDS_ROW + lane] = l;
        split_bf16(a1, h, l);
        sAh[r * LDS_ROW + lane + 32] = h; sAl[r * LDS_ROW + lane + 32] = l;
        split_bf16(s0v, h, l);
        sAh[r * LDS_ROW + 64 + lane] = h; sAl[r * LDS_ROW + 64 + lane] = l;
        split_bf16(s1v, h, l);
        sAh[r * LDS_ROW + 96 + lane] = h; sAl[r * LDS_ROW + 96 + lane] = l;
    }
    __syncthreads();

    // ---- GEMM1: 128x128, warp grid 4(M) x 4(N), warp tile 32x32 ----
    int Rb = (wid & 3) * 32;
    int Nb = (wid >> 2) * 32;
    int qr = lane >> 2;
    int qc = 2 * (lane & 3);

    float acc[2][4][4];
#pragma unroll
    for (int mt = 0; mt < 2; mt++)
#pragma unroll
        for (int nt = 0; nt < 4; nt++)
#pragma unroll
            for (int j = 0; j < 4; j++) acc[mt][nt][j] = 0.f;

    for (int ks = 0; ks < 8; ks++) {
        int kc = ks * 16 + qc;
        uint32_t ah[2][4], al[2][4];
#pragma unroll
        for (int mt = 0; mt < 2; mt++) {
            int r = Rb + mt * 16 + qr;
            ah[mt][0] = *(const uint32_t*)(sAh + r * LDS_ROW + kc);
            ah[mt][1] = *(const uint32_t*)(sAh + (r + 8) * LDS_ROW + kc);
            ah[mt][2] = *(const uint32_t*)(sAh + r * LDS_ROW + kc + 8);
            ah[mt][3] = *(const uint32_t*)(sAh + (r + 8) * LDS_ROW + kc + 8);
            al[mt][0] = *(const uint32_t*)(sAl + r * LDS_ROW + kc);
            al[mt][1] = *(const uint32_t*)(sAl + (r + 8) * LDS_ROW + kc);
            al[mt][2] = *(const uint32_t*)(sAl + r * LDS_ROW + kc + 8);
            al[mt][3] = *(const uint32_t*)(sAl + (r + 8) * LDS_ROW + kc + 8);
        }
#pragma unroll
        for (int nt = 0; nt < 4; nt++) {
            int nn = Nb + nt * 8 + qr;
            uint32_t bh0 = *(const uint32_t*)(sW1h + nn * LDS_ROW + kc);
            uint32_t bh1 = *(const uint32_t*)(sW1h + nn * LDS_ROW + kc + 8);
            uint32_t bl0 = *(const uint32_t*)(sW1l + nn * LDS_ROW + kc);
            uint32_t bl1 = *(const uint32_t*)(sW1l + nn * LDS_ROW + kc + 8);
#pragma unroll
            for (int mt = 0; mt < 2; mt++) {
                mma16816(acc[mt][nt], ah[mt], bh0, bh1);
                mma16816(acc[mt][nt], al[mt], bh0, bh1);
                mma16816(acc[mt][nt], ah[mt], bl0, bl1);
            }
        }
    }
    __syncthreads();  // done reading A; safe to overwrite with h1

    // ---- epilogue 1: bias + relu + resplit -> sAh/sAl (h1 tile) ----
#pragma unroll
    for (int mt = 0; mt < 2; mt++) {
#pragma unroll
        for (int nt = 0; nt < 4; nt++) {
            int c = Nb + nt * 8 + qc;
            float bv0 = sB[c], bv1 = sB[c + 1];
#pragma unroll
            for (int half = 0; half < 2; half++) {
                int r = Rb + mt * 16 + qr + half * 8;
                float v0 = acc[mt][nt][2 * half] + bv0;
                float v1 = acc[mt][nt][2 * half + 1] + bv1;
                v0 = v0 > 0.f ? v0 : 0.f;
                v1 = v1 > 0.f ? v1 : 0.f;
                __nv_bfloat16 h0, h1, l0, l1;
                split_bf16(v0, h0, l0);
                split_bf16(v1, h1, l1);
                __nv_bfloat162 ph = __nv_bfloat162(h0, h1);
                __nv_bfloat162 pl = __nv_bfloat162(l0, l1);
                *(uint32_t*)(sAh + r * LDS_ROW + c) = *(uint32_t*)&ph;
                *(uint32_t*)(sAl + r * LDS_ROW + c) = *(uint32_t*)&pl;
            }
        }
    }
    __syncthreads();

    // ---- GEMM2: 128x80, warp grid 8(M) x 2(N), warp tile 16x40 ----
    int Rb2 = (wid & 7) * 16;
    int Nb2 = (wid >> 3) * 40;

    float acc2[5][4];
#pragma unroll
    for (int nt = 0; nt < 5; nt++)
#pragma unroll
        for (int j = 0; j < 4; j++) acc2[nt][j] = 0.f;

    for (int ks = 0; ks < 8; ks++) {
        int kc = ks * 16 + qc;
        int r = Rb2 + qr;
        uint32_t ah[4], al[4];
        ah[0] = *(const uint32_t*)(sAh + r * LDS_ROW + kc);
        ah[1] = *(const uint32_t*)(sAh + (r + 8) * LDS_ROW + kc);
        ah[2] = *(const uint32_t*)(sAh + r * LDS_ROW + kc + 8);
        ah[3] = *(const uint32_t*)(sAh + (r + 8) * LDS_ROW + kc + 8);
        al[0] = *(const uint32_t*)(sAl + r * LDS_ROW + kc);
        al[1] = *(const uint32_t*)(sAl + (r + 8) * LDS_ROW + kc);
        al[2] = *(const uint32_t*)(sAl + r * LDS_ROW + kc + 8);
        al[3] = *(const uint32_t*)(sAl + (r + 8) * LDS_ROW + kc + 8);
#pragma unroll
        for (int nt = 0; nt < 5; nt++) {
            int nn = Nb2 + nt * 8 + qr;
            uint32_t bh0 = *(const uint32_t*)(sW2h + nn * LDS_ROW + kc);
            uint32_t bh1 = *(const uint32_t*)(sW2h + nn * LDS_ROW + kc + 8);
            uint32_t bl0 = *(const uint32_t*)(sW2l + nn * LDS_ROW + kc);
            uint32_t bl1 = *(const uint32_t*)(sW2l + nn * LDS_ROW + kc + 8);
            mma16816(acc2[nt], ah, bh0, bh1);
            mma16816(acc2[nt], al, bh0, bh1);
            mma16816(acc2[nt], ah, bl0, bl1);
        }
    }

    // ---- epilogue 2: write y2l (stride 48) / y2r (stride 40) ----
#pragma unroll
    for (int nt = 0; nt < 5; nt++) {
        int c = Nb2 + nt * 8 + qc;  // 0..78 even
        int n0 = base + Rb2 + qr;
        int n1 = n0 + 8;
        if (c < DOUT) {
            if (n0 < N_NODES)
                *(float2*)&g_y2l[(size_t)n0 * Y2L_STR + c] = make_float2(acc2[nt][0], acc2[nt][1]);
            if (n1 < N_NODES)
                *(float2*)&g_y2l[(size_t)n1 * Y2L_STR + c] = make_float2(acc2[nt][2], acc2[nt][3]);
        } else {
            int cc = c - DOUT;
            if (n0 < N_NODES)
                *(float2*)&g_y2r[(size_t)n0 * DOUT + cc] = make_float2(acc2[nt][0], acc2[nt][1]);
            if (n1 < N_NODES)
                *(float2*)&g_y2r[(size_t)n1 * DOUT + cc] = make_float2(acc2[nt][2], acc2[nt][3]);
        }
    }
}

// ---------------- final: out = log_softmax(mean-agg(y2l) + b2 + y2r) ------
__global__ void k_out(const float* __restrict__ b2, float* __restrict__ out) {
    int warp = (blockIdx.x * blockDim.x + threadIdx.x) >> 5;
    int lane = threadIdx.x & 31;
    if (warp >= N_NODES) return;
    float a0 = 0.f, a1 = 0.f, b0 = 0.f, b1v = 0.f;
    float c0 = 0.f, c1 = 0.f, d0 = 0.f, d1 = 0.f;
    int s0 = g_rowptr[warp], s1 = g_rowptr[warp + 1];
    int e = s0;
    for (; e + 3 < s1; e += 4) {
        const float* f0 = g_y2l + (size_t)g_col[e] * Y2L_STR;
        const float* f1 = g_y2l + (size_t)g_col[e + 1] * Y2L_STR;
        const float* f2 = g_y2l + (size_t)g_col[e + 2] * Y2L_STR;
        const float* f3 = g_y2l + (size_t)g_col[e + 3] * Y2L_STR;
        a0 += f0[lane];
        b0 += f1[lane];
        c0 += f2[lane];
        d0 += f3[lane];
        if (lane < 8) {
            a1 += f0[32 + lane];
            b1v += f1[32 + lane];
            c1 += f2[32 + lane];
            d1 += f3[32 + lane];
        }
    }
    for (; e < s1; e++) {
        const float* f0 = g_y2l + (size_t)g_col[e] * Y2L_STR;
        a0 += f0[lane];
        if (lane < 8) a1 += f0[32 + lane];
    }
    a0 += b0 + c0 + d0;
    a1 += b1v + c1 + d1;
    float inv = 1.f / (float)max(s1 - s0, 1);
    size_t nb = (size_t)warp * DOUT;
    float v0 = a0 * inv + b2[lane] + g_y2r[nb + lane];
    float v1 = (lane < 8) ? (a1 * inv + b2[32 + lane] + g_y2r[nb + 32 + lane])
                          : -INFINITY;
    float m = fmaxf(v0, v1);
    for (int off = 16; off; off >>= 1)
        m = fmaxf(m, __shfl_xor_sync(0xffffffffu, m, off));
    float s = expf(v0 - m) + ((lane < 8) ? expf(v1 - m) : 0.f);
    for (int off = 16; off; off >>= 1)
        s += __shfl_xor_sync(0xffffffffu, s, off);
    float lse = m + logf(s);
    out[nb + lane] = v0 - lse;
    if (lane < 8) out[nb + 32 + lane] = v1 - lse;
}

// ---------------- launch --------------------------------------------------
extern "C" void kernel_launch(void* const* d_in, const int* in_sizes, int n_in,
                              void* d_out, int out_size) {
    const float* x = (const float*)d_in[0];
    const void* ei = d_in[1];
    const float* W1l = (const float*)d_in[2];
    const float* b1 = (const float*)d_in[3];
    const float* W1r = (const float*)d_in[4];
    const float* W2l = (const float*)d_in[5];
    const float* b2 = (const float*)d_in[6];
    const float* W2r = (const float*)d_in[7];
    float* out = (float*)d_out;

    cudaFuncSetAttribute(k_fused, cudaFuncAttributeMaxDynamicSharedMemorySize,
                         SM_TOTAL);

    k_init<<<(N_NODES + 255) / 256, 256>>>((const int*)ei, W1l, W1r, W2l, W2r);
    k_hist<<<(N_EDGES + 255) / 256, 256>>>(ei);
    k_scan_block<<<SCAN_NB, SCAN_B>>>();
    k_scan_add<<<SCAN_NB, SCAN_B>>>();
    k_scatter<<<(N_EDGES + 255) / 256, 256>>>(ei);

    k_fused<<<N_TILES, 512, SM_TOTAL>>>(x, b1);
    k_out<<<(N_NODES * 32 + 255) / 256, 256>>>(b2, out);
}

// round 7
// speedup vs baseline: 1.0201x; 1.0201x over previous
#include <cuda_runtime.h>
#include <cuda_bf16.h>
#include <math.h>
#include <stdint.h>

#define N_NODES 100000
#define N_EDGES 1600000
#define DIN 64
#define DHID 128
#define DOUT 40
#define Y2L_STR 40
#define SCAN_B 512
#define SCAN_NB ((N_NODES + SCAN_B - 1) / SCAN_B)
#define TILE_M 128
#define N_TILES ((N_NODES + TILE_M - 1) / TILE_M)  // 782
#define W2ROWS 80
#define LDS_ROW 136  // bf16 elems per SMEM row (128 + 8 pad) -> conflict-free frags

// SMEM byte offsets for fused kernel
#define SM_AH 0
#define SM_AL 34816
#define SM_W1H 69632
#define SM_W1L 104448
#define SM_W2H 139264
#define SM_W2L 161024
#define SM_BIAS 182784
#define SM_TOTAL 183424

// ---------------- device scratch ----------------
__device__ int g_is64;
__device__ int g_deg[N_NODES];
__device__ int g_rowptr[N_NODES + 1];
__device__ int g_fill[N_NODES];
__device__ int g_col[N_EDGES];
__device__ int g_part[256];
__device__ uint32_t g_w1h[DHID * 64], g_w1l[DHID * 64];      // [128 out][128 k] bf16x2
__device__ uint32_t g_w2h[W2ROWS * 64], g_w2l[W2ROWS * 64];  // [80 out][128 k]
__device__ float g_y2l[(size_t)N_NODES * Y2L_STR];
__device__ float g_y2r[(size_t)N_NODES * DOUT];

// ---------------- helpers ----------------
__device__ __forceinline__ void mma16816(float* c, const uint32_t* a,
                                         uint32_t b0, uint32_t b1) {
    asm volatile(
        "mma.sync.aligned.m16n8k16.row.col.f32.bf16.bf16.f32 "
        "{%0,%1,%2,%3}, {%4,%5,%6,%7}, {%8,%9}, {%0,%1,%2,%3};"
        : "+f"(c[0]), "+f"(c[1]), "+f"(c[2]), "+f"(c[3])
        : "r"(a[0]), "r"(a[1]), "r"(a[2]), "r"(a[3]), "r"(b0), "r"(b1));
}
__device__ __forceinline__ void split_bf16(float v, __nv_bfloat16& h, __nv_bfloat16& l) {
    h = __float2bfloat16_rn(v);
    l = __float2bfloat16_rn(v - __bfloat162float(h));
}

// ---------------- edge index access (int64 or int32, runtime-detected) ----
__device__ __forceinline__ int edst(const void* ei, int e) {
    return g_is64 ? (int)((const long long*)ei)[(size_t)N_EDGES + e]
                  : ((const int*)ei)[(size_t)N_EDGES + e];
}
__device__ __forceinline__ int esrc(const void* ei, int e) {
    return g_is64 ? (int)((const long long*)ei)[e] : ((const int*)ei)[e];
}

// init degrees + dtype detect + weight split-conversion (one kernel)
__global__ void k_init(const int* ei,
                       const float* __restrict__ W1l, const float* __restrict__ W1r,
                       const float* __restrict__ W2l, const float* __restrict__ W2r) {
    int i = blockIdx.x * blockDim.x + threadIdx.x;
    if (i < N_NODES) g_deg[i] = 0;
    int tot1 = DHID * 64;
    if (i < tot1) {
        int o = i >> 6, c = 2 * (i & 63);
        float v0 = (c < 64) ? W1l[o * 64 + c] : W1r[o * 64 + c - 64];
        float v1 = (c < 64) ? W1l[o * 64 + c + 1] : W1r[o * 64 + c - 63];
        __nv_bfloat16 h0, h1, l0, l1;
        split_bf16(v0, h0, l0); split_bf16(v1, h1, l1);
        __nv_bfloat162 ph = __nv_bfloat162(h0, h1);
        __nv_bfloat162 pl = __nv_bfloat162(l0, l1);
        g_w1h[i] = *(uint32_t*)&ph;
        g_w1l[i] = *(uint32_t*)&pl;
    } else if (i < tot1 + W2ROWS * 64) {
        int j = i - tot1;
        int o = j >> 6, c = 2 * (j & 63);
        float v0 = (o < DOUT) ? W2l[o * DHID + c] : W2r[(o - DOUT) * DHID + c];
        float v1 = (o < DOUT) ? W2l[o * DHID + c + 1] : W2r[(o - DOUT) * DHID + c + 1];
        __nv_bfloat16 h0, h1, l0, l1;
        split_bf16(v0, h0, l0); split_bf16(v1, h1, l1);
        __nv_bfloat162 ph = __nv_bfloat162(h0, h1);
        __nv_bfloat162 pl = __nv_bfloat162(l0, l1);
        g_w2h[j] = *(uint32_t*)&ph;
        g_w2l[j] = *(uint32_t*)&pl;
    }
    if (blockIdx.x == 0) {
        bool ok = true;
        for (int j = threadIdx.x; j < 4096; j += blockDim.x)
            if (ei[2 * j + 1] != 0) ok = false;
        int all = __syncthreads_and((int)ok);
        if (threadIdx.x == 0) g_is64 = all ? 1 : 0;
    }
}
__global__ void k_hist(const void* ei) {
    int e = blockIdx.x * blockDim.x + threadIdx.x;
    if (e < N_EDGES) atomicAdd(&g_deg[edst(ei, e)], 1);
}
__global__ void k_scan_block() {
    __shared__ int s[SCAN_B];
    int i = blockIdx.x * SCAN_B + threadIdx.x;
    int v = (i < N_NODES) ? g_deg[i] : 0;
    s[threadIdx.x] = v;
    __syncthreads();
    for (int off = 1; off < SCAN_B; off <<= 1) {
        int t = (threadIdx.x >= off) ? s[threadIdx.x - off] : 0;
        __syncthreads();
        s[threadIdx.x] += t;
        __syncthreads();
    }
    if (i < N_NODES) g_rowptr[i] = s[threadIdx.x] - v;
    if (threadIdx.x == SCAN_B - 1) g_part[blockIdx.x] = s[SCAN_B - 1];
}
// each block redundantly scans the 196 partials in SMEM, then applies offset
__global__ void k_scan_add() {
    __shared__ int sp[256];
    int t = threadIdx.x;
    if (t < 256) sp[t] = (t < SCAN_NB) ? g_part[t] : 0;
    __syncthreads();
    for (int off = 1; off < 256; off <<= 1) {
        int v = (t < 256 && t >= off) ? sp[t - off] : 0;
        __syncthreads();
        if (t < 256) sp[t] += v;
        __syncthreads();
    }
    int offset = (blockIdx.x == 0) ? 0 : sp[blockIdx.x - 1];
    int i = blockIdx.x * SCAN_B + t;
    if (i < N_NODES) {
        int r = g_rowptr[i] + offset;
        g_rowptr[i] = r;
        g_fill[i] = r;
    }
    if (i == 0) g_rowptr[N_NODES] = N_EDGES;
}
__global__ void k_scatter(const void* ei) {
    int e = blockIdx.x * blockDim.x + threadIdx.x;
    if (e < N_EDGES) {
        int d = edst(ei, e);
        int p = atomicAdd(&g_fill[d], 1);
        g_col[p] = esrc(ei, e);
    }
}

// ---------------- fused: aggregate + GEMM1 + relu + GEMM2 -----------------
// Per CTA: 128 nodes. A/h1 tiles live entirely in SMEM (no global round-trip).
__global__ void __launch_bounds__(512) k_fused(const float* __restrict__ x,
                                               const float* __restrict__ b1) {
    extern __shared__ char dsm[];
    __nv_bfloat16* sAh = (__nv_bfloat16*)(dsm + SM_AH);
    __nv_bfloat16* sAl = (__nv_bfloat16*)(dsm + SM_AL);
    __nv_bfloat16* sW1h = (__nv_bfloat16*)(dsm + SM_W1H);
    __nv_bfloat16* sW1l = (__nv_bfloat16*)(dsm + SM_W1L);
    __nv_bfloat16* sW2h = (__nv_bfloat16*)(dsm + SM_W2H);
    __nv_bfloat16* sW2l = (__nv_bfloat16*)(dsm + SM_W2L);
    float* sB = (float*)(dsm + SM_BIAS);

    int tid = threadIdx.x, wid = tid >> 5, lane = tid & 31;
    int base = blockIdx.x * TILE_M;

    // ---- stage weights (pre-split bf16 in global) ----
    for (int i = tid; i < 128 * 16; i += 512) {
        int r = i >> 4, c8 = i & 15;
        *(uint4*)((char*)sW1h + r * (LDS_ROW * 2) + c8 * 16) = *(const uint4*)(g_w1h + r * 64 + c8 * 4);
        *(uint4*)((char*)sW1l + r * (LDS_ROW * 2) + c8 * 16) = *(const uint4*)(g_w1l + r * 64 + c8 * 4);
    }
    for (int i = tid; i < W2ROWS * 16; i += 512) {
        int r = i >> 4, c8 = i & 15;
        *(uint4*)((char*)sW2h + r * (LDS_ROW * 2) + c8 * 16) = *(const uint4*)(g_w2h + r * 64 + c8 * 4);
        *(uint4*)((char*)sW2l + r * (LDS_ROW * 2) + c8 * 16) = *(const uint4*)(g_w2l + r * 64 + c8 * 4);
    }
    if (tid < DHID) sB[tid] = b1[tid];

    // ---- gather-aggregate + self rows -> split into sAh/sAl ----
    // warp w handles rows w*8 .. w*8+7; lane covers cols (lane, lane+32)
#pragma unroll 1
    for (int i = 0; i < 8; i++) {
        int r = wid * 8 + i;
        int n = base + r;
        float a0 = 0.f, a1 = 0.f, c0 = 0.f, c1 = 0.f;
        float s0v = 0.f, s1v = 0.f;
        float inv = 1.f;
        if (n < N_NODES) {
            int s0 = g_rowptr[n], s1 = g_rowptr[n + 1];
            int e = s0;
            for (; e + 1 < s1; e += 2) {
                const float* f0 = x + (size_t)g_col[e] * DIN;
                const float* f1 = x + (size_t)g_col[e + 1] * DIN;
                a0 += f0[lane]; a1 += f0[lane + 32];
                c0 += f1[lane]; c1 += f1[lane + 32];
            }
            if (e < s1) {
                const float* f0 = x + (size_t)g_col[e] * DIN;
                a0 += f0[lane]; a1 += f0[lane + 32];
            }
            a0 += c0; a1 += c1;
            inv = 1.f / (float)max(s1 - s0, 1);
            s0v = x[(size_t)n * DIN + lane];
            s1v = x[(size_t)n * DIN + 32 + lane];
        }
        a0 *= inv; a1 *= inv;
        __nv_bfloat16 h, l;
        split_bf16(a0, h, l);
        sAh[r * LDS_ROW + lane] = h; sAl[r * LDS_ROW + lane] = l;
        split_bf16(a1, h, l);
        sAh[r * LDS_ROW + lane + 32] = h; sAl[r * LDS_ROW + lane + 32] = l;
        split_bf16(s0v, h, l);
        sAh[r * LDS_ROW + 64 + lane] = h; sAl[r * LDS_ROW + 64 + lane] = l;
        split_bf16(s1v, h, l);
        sAh[r * LDS_ROW + 96 + lane] = h; sAl[r * LDS_ROW + 96 + lane] = l;
    }
    __syncthreads();

    // ---- GEMM1: 128x128, warp grid 4(M) x 4(N), warp tile 32x32 ----
    int Rb = (wid & 3) * 32;
    int Nb = (wid >> 2) * 32;
    int qr = lane >> 2;
    int qc = 2 * (lane & 3);

    float acc[2][4][4];
#pragma unroll
    for (int mt = 0; mt < 2; mt++)
#pragma unroll
        for (int nt = 0; nt < 4; nt++)
#pragma unroll
            for (int j = 0; j < 4; j++) acc[mt][nt][j] = 0.f;

    for (int ks = 0; ks < 8; ks++) {
        int kc = ks * 16 + qc;
        uint32_t ah[2][4], al[2][4];
#pragma unroll
        for (int mt = 0; mt < 2; mt++) {
            int r = Rb + mt * 16 + qr;
            ah[mt][0] = *(const uint32_t*)(sAh + r * LDS_ROW + kc);
            ah[mt][1] = *(const uint32_t*)(sAh + (r + 8) * LDS_ROW + kc);
            ah[mt][2] = *(const uint32_t*)(sAh + r * LDS_ROW + kc + 8);
            ah[mt][3] = *(const uint32_t*)(sAh + (r + 8) * LDS_ROW + kc + 8);
            al[mt][0] = *(const uint32_t*)(sAl + r * LDS_ROW + kc);
            al[mt][1] = *(const uint32_t*)(sAl + (r + 8) * LDS_ROW + kc);
            al[mt][2] = *(const uint32_t*)(sAl + r * LDS_ROW + kc + 8);
            al[mt][3] = *(const uint32_t*)(sAl + (r + 8) * LDS_ROW + kc + 8);
        }
#pragma unroll
        for (int nt = 0; nt < 4; nt++) {
            int nn = Nb + nt * 8 + qr;
            uint32_t bh0 = *(const uint32_t*)(sW1h + nn * LDS_ROW + kc);
            uint32_t bh1 = *(const uint32_t*)(sW1h + nn * LDS_ROW + kc + 8);
            uint32_t bl0 = *(const uint32_t*)(sW1l + nn * LDS_ROW + kc);
            uint32_t bl1 = *(const uint32_t*)(sW1l + nn * LDS_ROW + kc + 8);
#pragma unroll
            for (int mt = 0; mt < 2; mt++) {
                mma16816(acc[mt][nt], ah[mt], bh0, bh1);
                mma16816(acc[mt][nt], al[mt], bh0, bh1);
                mma16816(acc[mt][nt], ah[mt], bl0, bl1);
            }
        }
    }
    __syncthreads();  // done reading A; safe to overwrite with h1

    // ---- epilogue 1: bias + relu + resplit -> sAh/sAl (h1 tile) ----
#pragma unroll
    for (int mt = 0; mt < 2; mt++) {
#pragma unroll
        for (int nt = 0; nt < 4; nt++) {
            int c = Nb + nt * 8 + qc;
            float bv0 = sB[c], bv1 = sB[c + 1];
#pragma unroll
            for (int half = 0; half < 2; half++) {
                int r = Rb + mt * 16 + qr + half * 8;
                float v0 = acc[mt][nt][2 * half] + bv0;
                float v1 = acc[mt][nt][2 * half + 1] + bv1;
                v0 = v0 > 0.f ? v0 : 0.f;
                v1 = v1 > 0.f ? v1 : 0.f;
                __nv_bfloat16 h0, h1, l0, l1;
                split_bf16(v0, h0, l0);
                split_bf16(v1, h1, l1);
                __nv_bfloat162 ph = __nv_bfloat162(h0, h1);
                __nv_bfloat162 pl = __nv_bfloat162(l0, l1);
                *(uint32_t*)(sAh + r * LDS_ROW + c) = *(uint32_t*)&ph;
                *(uint32_t*)(sAl + r * LDS_ROW + c) = *(uint32_t*)&pl;
            }
        }
    }
    __syncthreads();

    // ---- GEMM2: 128x80, warp grid 8(M) x 2(N), warp tile 16x40 ----
    int Rb2 = (wid & 7) * 16;
    int Nb2 = (wid >> 3) * 40;

    float acc2[5][4];
#pragma unroll
    for (int nt = 0; nt < 5; nt++)
#pragma unroll
        for (int j = 0; j < 4; j++) acc2[nt][j] = 0.f;

    for (int ks = 0; ks < 8; ks++) {
        int kc = ks * 16 + qc;
        int r = Rb2 + qr;
        uint32_t ah[4], al[4];
        ah[0] = *(const uint32_t*)(sAh + r * LDS_ROW + kc);
        ah[1] = *(const uint32_t*)(sAh + (r + 8) * LDS_ROW + kc);
        ah[2] = *(const uint32_t*)(sAh + r * LDS_ROW + kc + 8);
        ah[3] = *(const uint32_t*)(sAh + (r + 8) * LDS_ROW + kc + 8);
        al[0] = *(const uint32_t*)(sAl + r * LDS_ROW + kc);
        al[1] = *(const uint32_t*)(sAl + (r + 8) * LDS_ROW + kc);
        al[2] = *(const uint32_t*)(sAl + r * LDS_ROW + kc + 8);
        al[3] = *(const uint32_t*)(sAl + (r + 8) * LDS_ROW + kc + 8);
#pragma unroll
        for (int nt = 0; nt < 5; nt++) {
            int nn = Nb2 + nt * 8 + qr;
            uint32_t bh0 = *(const uint32_t*)(sW2h + nn * LDS_ROW + kc);
            uint32_t bh1 = *(const uint32_t*)(sW2h + nn * LDS_ROW + kc + 8);
            uint32_t bl0 = *(const uint32_t*)(sW2l + nn * LDS_ROW + kc);
            uint32_t bl1 = *(const uint32_t*)(sW2l + nn * LDS_ROW + kc + 8);
            mma16816(acc2[nt], ah, bh0, bh1);
            mma16816(acc2[nt], al, bh0, bh1);
            mma16816(acc2[nt], ah, bl0, bl1);
        }
    }

    // ---- epilogue 2: write y2l / y2r ----
#pragma unroll
    for (int nt = 0; nt < 5; nt++) {
        int c = Nb2 + nt * 8 + qc;  // 0..78 even
        int n0 = base + Rb2 + qr;
        int n1 = n0 + 8;
        if (c < DOUT) {
            if (n0 < N_NODES)
                *(float2*)&g_y2l[(size_t)n0 * Y2L_STR + c] = make_float2(acc2[nt][0], acc2[nt][1]);
            if (n1 < N_NODES)
                *(float2*)&g_y2l[(size_t)n1 * Y2L_STR + c] = make_float2(acc2[nt][2], acc2[nt][3]);
        } else {
            int cc = c - DOUT;
            if (n0 < N_NODES)
                *(float2*)&g_y2r[(size_t)n0 * DOUT + cc] = make_float2(acc2[nt][0], acc2[nt][1]);
            if (n1 < N_NODES)
                *(float2*)&g_y2r[(size_t)n1 * DOUT + cc] = make_float2(acc2[nt][2], acc2[nt][3]);
        }
    }
}

// ---------------- final: out = log_softmax(mean-agg(y2l) + b2 + y2r) ------
__global__ void k_out(const float* __restrict__ b2, float* __restrict__ out) {
    int warp = (blockIdx.x * blockDim.x + threadIdx.x) >> 5;
    int lane = threadIdx.x & 31;
    if (warp >= N_NODES) return;
    float a0 = 0.f, a1 = 0.f, b0 = 0.f, b1v = 0.f;
    float c0 = 0.f, c1 = 0.f, d0 = 0.f, d1 = 0.f;
    int s0 = g_rowptr[warp], s1 = g_rowptr[warp + 1];
    int e = s0;
    for (; e + 3 < s1; e += 4) {
        const float* f0 = g_y2l + (size_t)g_col[e] * Y2L_STR;
        const float* f1 = g_y2l + (size_t)g_col[e + 1] * Y2L_STR;
        const float* f2 = g_y2l + (size_t)g_col[e + 2] * Y2L_STR;
        const float* f3 = g_y2l + (size_t)g_col[e + 3] * Y2L_STR;
        a0 += f0[lane];
        b0 += f1[lane];
        c0 += f2[lane];
        d0 += f3[lane];
        if (lane < 8) {
            a1 += f0[32 + lane];
            b1v += f1[32 + lane];
            c1 += f2[32 + lane];
            d1 += f3[32 + lane];
        }
    }
    for (; e < s1; e++) {
        const float* f0 = g_y2l + (size_t)g_col[e] * Y2L_STR;
        a0 += f0[lane];
        if (lane < 8) a1 += f0[32 + lane];
    }
    a0 += b0 + c0 + d0;
    a1 += b1v + c1 + d1;
    float inv = 1.f / (float)max(s1 - s0, 1);
    size_t nb = (size_t)warp * DOUT;
    float v0 = a0 * inv + b2[lane] + g_y2r[nb + lane];
    float v1 = (lane < 8) ? (a1 * inv + b2[32 + lane] + g_y2r[nb + 32 + lane])
                          : -INFINITY;
    float m = fmaxf(v0, v1);
    for (int off = 16; off; off >>= 1)
        m = fmaxf(m, __shfl_xor_sync(0xffffffffu, m, off));
    float s = expf(v0 - m) + ((lane < 8) ? expf(v1 - m) : 0.f);
    for (int off = 16; off; off >>= 1)
        s += __shfl_xor_sync(0xffffffffu, s, off);
    float lse = m + logf(s);
    out[nb + lane] = v0 - lse;
    if (lane < 8) out[nb + 32 + lane] = v1 - lse;
}

// ---------------- launch --------------------------------------------------
extern "C" void kernel_launch(void* const* d_in, const int* in_sizes, int n_in,
                              void* d_out, int out_size) {
    const float* x = (const float*)d_in[0];
    const void* ei = d_in[1];
    const float* W1l = (const float*)d_in[2];
    const float* b1 = (const float*)d_in[3];
    const float* W1r = (const float*)d_in[4];
    const float* W2l = (const float*)d_in[5];
    const float* b2 = (const float*)d_in[6];
    const float* W2r = (const float*)d_in[7];
    float* out = (float*)d_out;

    cudaFuncSetAttribute(k_fused, cudaFuncAttributeMaxDynamicSharedMemorySize,
                         SM_TOTAL);

    k_init<<<(N_NODES + 255) / 256, 256>>>((const int*)ei, W1l, W1r, W2l, W2r);
    k_hist<<<(N_EDGES + 255) / 256, 256>>>(ei);
    k_scan_block<<<SCAN_NB, SCAN_B>>>();
    k_scan_add<<<SCAN_NB, SCAN_B>>>();
    k_scatter<<<(N_EDGES + 255) / 256, 256>>>(ei);

    k_fused<<<N_TILES, 512, SM_TOTAL>>>(x, b1);
    k_out<<<(N_NODES * 32 + 255) / 256, 256>>>(b2, out);
}